// round 10
// baseline (speedup 1.0000x reference)
#include <cuda_runtime.h>

#define N_CAP 20480
#define E_CAP 327680
#define DEG_CAP 64      // fixed-stride edge-table width; deg ~ Poisson(16)
#define CH 16           // edges per accumulation chunk (8 subtask threads/edge)

// ---------------- device scratch ----------------
// d_count is zero at module load; ps_kernel re-zeros its node at the end of
// every call, so each graph replay starts from a clean cursor.
__device__ int d_count[N_CAP];
__device__ int d_elist[N_CAP * DEG_CAP];
__device__ float4 d_erec[E_CAP];   // per-edge: (pos[j]+shift@cell, j|sp<<24)

// ---------------- phase 1: scatter + edge-record packing -------------------
__global__ void scatter_kernel(const int* __restrict__ ei,
                               const float* __restrict__ pos,
                               const int* __restrict__ species,
                               const int* __restrict__ shifts,
                               const float* __restrict__ cells, int E) {
    int e = blockIdx.x * blockDim.x + threadIdx.x;
    if (e >= E) return;
    int i = ei[e];
    int j = ei[E + e];
    float px = pos[3 * j + 0];
    float py = pos[3 * j + 1];
    float pz = pos[3 * j + 2];
    float sx = (float)shifts[3 * e + 0];
    float sy = (float)shifts[3 * e + 1];
    float sz = (float)shifts[3 * e + 2];
    px += sx * cells[0] + sy * cells[3] + sz * cells[6];
    py += sx * cells[1] + sy * cells[4] + sz * cells[7];
    pz += sx * cells[2] + sy * cells[5] + sz * cells[8];
    int sp = species[j];
    d_erec[e] = make_float4(px, py, pz, __int_as_float(j | (sp << 24)));
    int p = atomicAdd(&d_count[i], 1);
    if (p < DEG_CAP) d_elist[i * DEG_CAP + p] = e;
}

// ---------------- phase 2: per-node features + power spectrum --------------
__global__ __launch_bounds__(128, 12) void ps_kernel(
    const float* __restrict__ pos, const float* __restrict__ embed,
    const float* __restrict__ mu, const float* __restrict__ sigma,
    float* __restrict__ out, int N)
{
    __shared__ __align__(16) float Ysh[CH][16];     // [edge][m]: 64B rows
    __shared__ __align__(16) float wsh_t[32][20];   // [q][edge], pad 20: f4 rows
    __shared__ __align__(16) float csh[16][32];     // [m][q]
    __shared__ int   elist[DEG_CAP];
    __shared__ int   esort[DEG_CAP];
    __shared__ float s_embed[16];
    __shared__ float s_mu[8];
    __shared__ float s_pi[3];

    int node = blockIdx.x;
    int t = threadIdx.x;

    if (t < 16) s_embed[t] = embed[t];
    if (t < 8)  s_mu[t] = mu[t];
    if (t < 3)  s_pi[t] = pos[3 * node + t];

    int deg = d_count[node];
    if (deg > DEG_CAP) deg = DEG_CAP;

    for (int k = t; k < deg; k += 128) elist[k] = d_elist[node * DEG_CAP + k];
    __syncthreads();
    // deterministic accumulation order: rank-sort unique edge ids
    for (int k = t; k < deg; k += 128) {
        int e = elist[k], rank = 0;
        for (int x = 0; x < deg; x++) rank += (elist[x] < e);
        esort[rank] = e;
    }
    __syncthreads();

    float sg = sigma[0];
    float inv2s2 = 1.0f / (2.0f * sg * sg);

    int w = t >> 5;   // warp id: owns m = 4w..4w+3
    int q = t & 31;   // lane
    float cacc0 = 0.0f, cacc1 = 0.0f, cacc2 = 0.0f, cacc3 = 0.0f;

    int eidx = t >> 3;   // 0..15: edge within chunk
    int sub  = t & 7;    // 0..7: subtask

    for (int base = 0; base < deg; base += CH) {
        int ne = deg - base; if (ne > CH) ne = CH;
        if (eidx < ne) {
            int e = esort[base + eidx];
            float4 rec = __ldg(&d_erec[e]);   // one broadcast LDG.128 per edge
            float rx = rec.x - s_pi[0];
            float ry = rec.y - s_pi[1];
            float rz = rec.z - s_pi[2];
            int sp = __float_as_int(rec.w) >> 24;

            float r2 = rx * rx + ry * ry + rz * rz + 1e-12f;
            float rinv = rsqrtf(r2);
            float r = r2 * rinv;
            float x = rx * rinv, y = ry * rinv, z = rz * rinv;

            float fcut = (r < 5.0f) ? 0.5f * (cospif(r * 0.2f) + 1.0f) : 0.0f;

            {   // radial: this thread owns n = sub -> q rows {8p+sub}
                float d = r - s_mu[sub];
                float Rn = __expf(-d * d * inv2s2) * fcut;
                wsh_t[0 * 8 + sub][eidx] = s_embed[4 * sp + 0] * Rn;
                wsh_t[1 * 8 + sub][eidx] = s_embed[4 * sp + 1] * Rn;
                wsh_t[2 * 8 + sub][eidx] = s_embed[4 * sp + 2] * Rn;
                wsh_t[3 * 8 + sub][eidx] = s_embed[4 * sp + 3] * Rn;
            }
            // spherical harmonics: this thread owns m = 2*sub, 2*sub+1
            float x2 = x * x, y2 = y * y, z2 = z * z;
            float ya, yb;
            switch (sub) {
                case 0: ya = 0.28209479177387814f;
                        yb = 0.4886025119029199f * y; break;
                case 1: ya = 0.4886025119029199f * z;
                        yb = 0.4886025119029199f * x; break;
                case 2: ya = 1.0925484305920792f * x * y;
                        yb = 1.0925484305920792f * y * z; break;
                case 3: ya = 0.31539156525252005f * (3.0f * z2 - 1.0f);
                        yb = 1.0925484305920792f * x * z; break;
                case 4: ya = 0.5462742152960396f * (x2 - y2);
                        yb = 0.5900435899266435f * y * (3.0f * x2 - y2); break;
                case 5: ya = 2.890611442640554f * x * y * z;
                        yb = 0.4570457994644658f * y * (5.0f * z2 - 1.0f); break;
                case 6: ya = 0.3731763325901154f * z * (5.0f * z2 - 3.0f);
                        yb = 0.4570457994644658f * x * (5.0f * z2 - 1.0f); break;
                default: ya = 1.445305721320277f * z * (x2 - y2);
                         yb = 0.5900435899266435f * x * (x2 - 3.0f * y2); break;
            }
            *(float2*)&Ysh[eidx][2 * sub] = make_float2(ya, yb);
        } else {
            // zero-fill tail edges: accumulate loop is always full 16
            wsh_t[0 * 8 + sub][eidx] = 0.0f;
            wsh_t[1 * 8 + sub][eidx] = 0.0f;
            wsh_t[2 * 8 + sub][eidx] = 0.0f;
            wsh_t[3 * 8 + sub][eidx] = 0.0f;
            *(float2*)&Ysh[eidx][2 * sub] = make_float2(0.0f, 0.0f);
        }
        __syncthreads();
        // preload this thread's 16 w-values as 4 x LDS.128 (conflict-free)
        float wreg[16];
        *(float4*)&wreg[0]  = *(const float4*)&wsh_t[q][0];
        *(float4*)&wreg[4]  = *(const float4*)&wsh_t[q][4];
        *(float4*)&wreg[8]  = *(const float4*)&wsh_t[q][8];
        *(float4*)&wreg[12] = *(const float4*)&wsh_t[q][12];
        const float4* Y4 = (const float4*)Ysh;   // [edge][4] float4s
#pragma unroll
        for (int e2i = 0; e2i < CH; e2i++) {
            float wv = wreg[e2i];
            float4 yv = Y4[e2i * 4 + w];         // broadcast LDS.128
            cacc0 = fmaf(yv.x, wv, cacc0);
            cacc1 = fmaf(yv.y, wv, cacc1);
            cacc2 = fmaf(yv.z, wv, cacc2);
            cacc3 = fmaf(yv.w, wv, cacc3);
        }
        __syncthreads();
    }

    csh[4 * w + 0][q] = cacc0;
    csh[4 * w + 1][q] = cacc1;
    csh[4 * w + 2][q] = cacc2;
    csh[4 * w + 3][q] = cacc3;
    __syncthreads();

    // epilogue: 64 threads, each owns a 4x4 tile (q-quad qp, r-quad rb).
    // Per m: one broadcast LDS.128 (ap = c[m][4qp..]) + one LDS.128
    // (v = c[m][4rb..]) -> 2 wavefronts/m/warp, 2 warps. Stores: STG.128,
    // 8 consecutive threads cover a full 128B line.
    if (t < 64) {
        int rb = t & 7;            // r-col quad
        int qp = t >> 3;           // 0..7: q-row quad
        const float4* csh4 = (const float4*)csh;   // [m][8]
        float4* out4 = (float4*)(out + (size_t)node * 4096);
        const float cgv[4] = {1.0f, 0.5773502691896258f,
                              0.4472135954999579f, 0.3779644730092272f};
        int m0 = 0;
#pragma unroll
        for (int l = 0; l < 4; l++) {
            int cnt = 2 * l + 1;
            float4 a0 = make_float4(0.f, 0.f, 0.f, 0.f);
            float4 a1 = make_float4(0.f, 0.f, 0.f, 0.f);
            float4 a2 = make_float4(0.f, 0.f, 0.f, 0.f);
            float4 a3 = make_float4(0.f, 0.f, 0.f, 0.f);
#pragma unroll 7
            for (int k = 0; k < 7; k++) {
                if (k < cnt) {
                    float4 v  = csh4[(m0 + k) * 8 + rb];
                    float4 ap = csh4[(m0 + k) * 8 + qp];
                    a0.x = fmaf(ap.x, v.x, a0.x);
                    a0.y = fmaf(ap.x, v.y, a0.y);
                    a0.z = fmaf(ap.x, v.z, a0.z);
                    a0.w = fmaf(ap.x, v.w, a0.w);
                    a1.x = fmaf(ap.y, v.x, a1.x);
                    a1.y = fmaf(ap.y, v.y, a1.y);
                    a1.z = fmaf(ap.y, v.z, a1.z);
                    a1.w = fmaf(ap.y, v.w, a1.w);
                    a2.x = fmaf(ap.z, v.x, a2.x);
                    a2.y = fmaf(ap.z, v.y, a2.y);
                    a2.z = fmaf(ap.z, v.z, a2.z);
                    a2.w = fmaf(ap.z, v.w, a2.w);
                    a3.x = fmaf(ap.w, v.x, a3.x);
                    a3.y = fmaf(ap.w, v.y, a3.y);
                    a3.z = fmaf(ap.w, v.z, a3.z);
                    a3.w = fmaf(ap.w, v.w, a3.w);
                }
            }
            float cg = cgv[l];
            a0.x *= cg; a0.y *= cg; a0.z *= cg; a0.w *= cg;
            a1.x *= cg; a1.y *= cg; a1.z *= cg; a1.w *= cg;
            a2.x *= cg; a2.y *= cg; a2.z *= cg; a2.w *= cg;
            a3.x *= cg; a3.y *= cg; a3.z *= cg; a3.w *= cg;
            float4* ob = out4 + l * 256 + qp * 32 + rb;
            __stcs(ob +  0, a0);
            __stcs(ob +  8, a1);
            __stcs(ob + 16, a2);
            __stcs(ob + 24, a3);
            m0 += cnt;
        }
    }

    // reset cursor for the next graph replay
    if (t == 0) d_count[node] = 0;
}

extern "C" void kernel_launch(void* const* d_in, const int* in_sizes, int n_in,
                              void* d_out, int out_size) {
    const float* pos     = (const float*)d_in[0];
    const float* cells   = (const float*)d_in[1];
    const int*   species = (const int*)  d_in[2];
    const int*   ei      = (const int*)  d_in[3];
    const int*   shifts  = (const int*)  d_in[4];
    const float* embed   = (const float*)d_in[5];
    const float* mu      = (const float*)d_in[6];
    const float* sigma   = (const float*)d_in[7];
    int N = in_sizes[0] / 3;
    int E = in_sizes[3] / 2;
    float* out = (float*)d_out;

    scatter_kernel<<<(E + 255) / 256, 256>>>(ei, pos, species, shifts, cells, E);
    ps_kernel<<<N, 128>>>(pos, embed, mu, sigma, out, N);
}